// round 5
// baseline (speedup 1.0000x reference)
#include <cuda_runtime.h>
#include <cuda_bf16.h>
#include <cstdint>

#define G_NUM 128
#define C_NUM 256
#define D_NUM 128
#define N_NODES_C 262144

// Scratch (device globals — no allocation allowed)
__device__ uint32_t g_cent[C_NUM * (D_NUM / 2)];   // centroids as packed bf16 pairs
__device__ float    g_c_sq[C_NUM];
__device__ float    g_sums[G_NUM * C_NUM];
__device__ int      g_counts[G_NUM];

// ---------------------------------------------------------------------------
__global__ void zero_sums_kernel() {
    int i = blockIdx.x * blockDim.x + threadIdx.x;
    if (i < G_NUM * C_NUM) g_sums[i] = 0.f;
}

// one block (32 threads) per centroid: convert to bf16, compute c_sq from bf16
__global__ void prep_cent_kernel(const float* __restrict__ cent) {
    int c = blockIdx.x;
    int t = threadIdx.x;  // 0..31
    float4 v = ((const float4*)cent)[c * 32 + t];
    __nv_bfloat162 p0 = __floats2bfloat162_rn(v.x, v.y);
    __nv_bfloat162 p1 = __floats2bfloat162_rn(v.z, v.w);
    g_cent[c * 64 + t * 2]     = *(uint32_t*)&p0;
    g_cent[c * 64 + t * 2 + 1] = *(uint32_t*)&p1;
    float a = __bfloat162float(p0.x), b = __bfloat162float(p0.y);
    float e = __bfloat162float(p1.x), f = __bfloat162float(p1.y);
    float s = a * a + b * b + e * e + f * f;
    #pragma unroll
    for (int off = 16; off; off >>= 1) s += __shfl_down_sync(0xffffffffu, s, off);
    if (t == 0) g_c_sq[c] = s;
}

// batch is sorted: per-graph counts via binary search (no atomics)
__global__ void counts_kernel(const int* __restrict__ batch) {
    int g = threadIdx.x;  // 0..127
    if (g >= G_NUM) return;
    int lo = 0, hi = N_NODES_C;
    while (lo < hi) { int m = (lo + hi) >> 1; if (batch[m] < g) lo = m + 1; else hi = m; }
    int lo2 = lo, hi2 = N_NODES_C;
    // lower bound of g+1, starting from lo
    {
        int a = lo2, b = hi2;
        while (a < b) { int m = (a + b) >> 1; if (batch[m] < g + 1) a = m + 1; else b = m; }
        g_counts[g] = a - lo;
    }
}

// ---------------------------------------------------------------------------
// Main: 128 (nodes) x 128 (centroids) tile per block; K=128 fully staged.
// 8 warps in 4(M) x 2(N); each warp: 32x64 via mma.m16n8k16 bf16.
#define SA_STRIDE 68    // u32 per row (= 136 bf16; padding kills bank conflicts)
#define SD_STRIDE 132   // floats per row for dist tile
#define SMEM_BYTES 71168

__global__ void __launch_bounds__(256, 2)
centroid_main_kernel(const float* __restrict__ x, const int* __restrict__ batch) {
    extern __shared__ char smem[];
    uint32_t* sA = (uint32_t*)smem;          // 128*68 u32 = 34816 B (bf16 x tile)
    uint32_t* sB = sA + 128 * SA_STRIDE;     // 34816 B (bf16 centroid tile)
    float*    sD = (float*)smem;             // aliases sA/sB after sync (67584 B)
    float* sXsq   = (float*)(smem + 69632);  // 128 f32
    float* sCsq   = (float*)(smem + 70144);  // 128 f32
    int*   sBatch = (int*)  (smem + 70656);  // 128 i32

    const int tid  = threadIdx.x;
    const int lane = tid & 31;
    const int warp = tid >> 5;
    const int bm = blockIdx.x;     // node tile (2048)
    const int by = blockIdx.y;     // centroid half (0/1)
    const int wm = (warp >> 1) * 32;
    const int wn = (warp & 1) * 64;
    const int gid = lane >> 2;     // 0..7
    const int kq  = lane & 3;      // 0..3

    // Load centroid tile (already bf16-packed): 8192 u32, coalesced
    {
        const uint32_t* src = g_cent + (size_t)by * 128 * 64;
        #pragma unroll
        for (int i = 0; i < 32; i++) {
            int idx = tid + i * 256;            // 0..8191
            int row = idx >> 6, cp = idx & 63;
            sB[row * SA_STRIDE + cp] = src[idx];
        }
    }
    // Load x tile (fp32 -> bf16), coalesced float4
    {
        const float4* src = (const float4*)(x + (size_t)bm * 128 * 128);
        #pragma unroll
        for (int i = 0; i < 16; i++) {
            int fidx = i * 1024 + tid * 4;
            float4 v = src[fidx >> 2];
            int row = fidx >> 7, col = fidx & 127;
            __nv_bfloat162 p0 = __floats2bfloat162_rn(v.x, v.y);
            __nv_bfloat162 p1 = __floats2bfloat162_rn(v.z, v.w);
            uint2 pk = make_uint2(*(uint32_t*)&p0, *(uint32_t*)&p1);
            *(uint2*)&sA[row * SA_STRIDE + (col >> 1)] = pk;
        }
    }
    if (tid < 128) {
        sBatch[tid] = batch[bm * 128 + tid];
        sCsq[tid]   = g_c_sq[by * 128 + tid];
    }
    __syncthreads();

    // x_sq from the bf16-quantized data (exact Gram identity)
    if (tid < 128) {
        float s = 0.f;
        #pragma unroll
        for (int j = 0; j < 64; j++) {
            uint32_t p = sA[tid * SA_STRIDE + j];
            __nv_bfloat162 h = *(__nv_bfloat162*)&p;
            float a = __bfloat162float(h.x), b = __bfloat162float(h.y);
            s = fmaf(a, a, s); s = fmaf(b, b, s);
        }
        sXsq[tid] = s;
    }

    float acc[2][8][4];
    #pragma unroll
    for (int mt = 0; mt < 2; mt++)
        #pragma unroll
        for (int nt = 0; nt < 8; nt++)
            #pragma unroll
            for (int q = 0; q < 4; q++) acc[mt][nt][q] = 0.f;

    #pragma unroll
    for (int ks = 0; ks < 8; ks++) {
        int kw = ks * 8 + kq;  // u32 offset: k0/2 + (lane&3)
        uint32_t afr[2][4];
        #pragma unroll
        for (int mt = 0; mt < 2; mt++) {
            int r0 = wm + mt * 16 + gid;
            afr[mt][0] = sA[r0 * SA_STRIDE + kw];
            afr[mt][1] = sA[(r0 + 8) * SA_STRIDE + kw];
            afr[mt][2] = sA[r0 * SA_STRIDE + kw + 4];
            afr[mt][3] = sA[(r0 + 8) * SA_STRIDE + kw + 4];
        }
        #pragma unroll
        for (int nt = 0; nt < 8; nt++) {
            int c0 = wn + nt * 8 + gid;
            uint32_t b0 = sB[c0 * SA_STRIDE + kw];
            uint32_t b1 = sB[c0 * SA_STRIDE + kw + 4];
            #pragma unroll
            for (int mt = 0; mt < 2; mt++) {
                asm volatile(
                    "mma.sync.aligned.m16n8k16.row.col.f32.bf16.bf16.f32 "
                    "{%0,%1,%2,%3}, {%4,%5,%6,%7}, {%8,%9}, {%0,%1,%2,%3};\n"
                    : "+f"(acc[mt][nt][0]), "+f"(acc[mt][nt][1]),
                      "+f"(acc[mt][nt][2]), "+f"(acc[mt][nt][3])
                    : "r"(afr[mt][0]), "r"(afr[mt][1]), "r"(afr[mt][2]), "r"(afr[mt][3]),
                      "r"(b0), "r"(b1));
            }
        }
    }
    __syncthreads();   // sA/sB reads done; sXsq visible to all

    // Epilogue: distance -> sD (aliases sA/sB)
    #pragma unroll
    for (int mt = 0; mt < 2; mt++) {
        int r = wm + mt * 16 + gid;
        float xs0 = sXsq[r], xs1 = sXsq[r + 8];
        #pragma unroll
        for (int nt = 0; nt < 8; nt++) {
            int c = wn + nt * 8 + kq * 2;
            float cs0 = sCsq[c], cs1 = sCsq[c + 1];
            float d00 = fmaxf(xs0 + cs0 - 2.f * acc[mt][nt][0], 0.f);
            float d01 = fmaxf(xs0 + cs1 - 2.f * acc[mt][nt][1], 0.f);
            float d10 = fmaxf(xs1 + cs0 - 2.f * acc[mt][nt][2], 0.f);
            float d11 = fmaxf(xs1 + cs1 - 2.f * acc[mt][nt][3], 0.f);
            *(float2*)&sD[r * SD_STRIDE + c]       = make_float2(sqrtf(d00), sqrtf(d01));
            *(float2*)&sD[(r + 8) * SD_STRIDE + c] = make_float2(sqrtf(d10), sqrtf(d11));
        }
    }
    __syncthreads();

    // Segmented per-column reduction (batch sorted -> few atomics per column)
    {
        int col = tid & 127;
        int rh  = tid >> 7;            // uniform per warp
        int rbase = rh * 64;
        float accum = 0.f;
        int curg = sBatch[rbase];
        #pragma unroll 4
        for (int r = rbase; r < rbase + 64; r++) {
            int gg = sBatch[r];
            if (gg != curg) {
                atomicAdd(&g_sums[curg * C_NUM + by * 128 + col], accum);
                accum = 0.f; curg = gg;
            }
            accum += sD[r * SD_STRIDE + col];
        }
        atomicAdd(&g_sums[curg * C_NUM + by * 128 + col], accum);
    }
}

// ---------------------------------------------------------------------------
__global__ void finalize_kernel(float* __restrict__ out) {
    int g = blockIdx.x, c = threadIdx.x;
    float cnt = (float)(g_counts[g] > 1 ? g_counts[g] : 1);
    out[g * C_NUM + c] = g_sums[g * C_NUM + c] / cnt;
}

// ---------------------------------------------------------------------------
extern "C" void kernel_launch(void* const* d_in, const int* in_sizes, int n_in,
                              void* d_out, int out_size) {
    const float* x     = (const float*)d_in[0];
    const int*   batch = (const int*)d_in[1];
    const float* cent  = (const float*)d_in[2];
    float* out = (float*)d_out;

    cudaFuncSetAttribute(centroid_main_kernel,
                         cudaFuncAttributeMaxDynamicSharedMemorySize, SMEM_BYTES);

    zero_sums_kernel<<<128, 256>>>();
    prep_cent_kernel<<<C_NUM, 32>>>(cent);
    counts_kernel<<<1, 128>>>(batch);
    dim3 grid(N_NODES_C / 128, 2);
    centroid_main_kernel<<<grid, 256, SMEM_BYTES>>>(x, batch);
    finalize_kernel<<<G_NUM, 256>>>(out);
}